// round 9
// baseline (speedup 1.0000x reference)
#include <cuda_runtime.h>
#include <cuda_bf16.h>
#include <math.h>
#include <stdint.h>

// Problem constants
#define B_  8
#define T_  1024
#define C_  1024
#define H_  16
#define M_  (B_*T_)      // 8192 rows
#define N3  (3*C_)       // 3072
#define K3  (3*C_)       // tripled-K for bf16x3 GEMMs

// ---------------------------------------------------------------------------
// Scratch (static __device__ arrays: no allocation allowed)
// ---------------------------------------------------------------------------
__device__ __nv_bfloat16 g_xn3  [(size_t)M_*K3];   // LN output, triple-bf16 (A-side)
__device__ __nv_bfloat16 g_wqkv3[(size_t)K3*N3];   // QKV weights [3k][n] triple (B-side)
__device__ __nv_bfloat16 g_q3   [(size_t)M_*K3];   // Q, scaled, A-side triple [row][3*(h*64+d)]
__device__ __nv_bfloat16 g_k3   [(size_t)M_*K3];   // K, B-side triple        [row][3*(h*64+d)]
__device__ __nv_bfloat16 g_v3   [(size_t)B_*H_*3*T_*64];  // V triple-rows [(b*H+h)*3T + 3s+j][64]
__device__ __nv_bfloat16 g_attn3[(size_t)M_*K3];   // attention out, triple-bf16
__device__ float         g_x1   [(size_t)M_*C_];   // x + attn proj (residual stream)
__device__ __nv_bfloat16 g_h3   [(size_t)M_*K3];   // MLP hidden, triple-bf16
__device__ __nv_bfloat16 g_wp3  [(size_t)K3*C_];   // Wproj triple
__device__ __nv_bfloat16 g_w13  [(size_t)K3*C_];   // W1 triple
__device__ __nv_bfloat16 g_w23  [(size_t)K3*C_];   // W2 triple

// ---------------------------------------------------------------------------
// bf16 hi/lo split helpers
// Triple pattern along K': A-side = (hi, lo, hi); B-side = (hi, hi, lo)
// ---------------------------------------------------------------------------
__device__ __forceinline__ uint32_t bfbits(float f) {
    return (uint32_t)__bfloat16_as_ushort(__float2bfloat16_rn(f));
}
__device__ __forceinline__ float bf2f(uint32_t u) {
    return __bfloat162float(__ushort_as_bfloat16((unsigned short)u));
}
__device__ __forceinline__ void split_pair(float v0, float v1,
                                           uint32_t& w0, uint32_t& w1, uint32_t& w2) {
    uint32_t h0 = bfbits(v0); uint32_t l0 = bfbits(v0 - bf2f(h0));
    uint32_t h1 = bfbits(v1); uint32_t l1 = bfbits(v1 - bf2f(h1));
    w0 = h0 | (l0 << 16);
    w1 = h0 | (h1 << 16);
    w2 = l1 | (h1 << 16);
}

// ---------------------------------------------------------------------------
// PTX wrappers
// ---------------------------------------------------------------------------
__device__ __forceinline__ void cp16(void* s, const void* g) {
    uint32_t sa = (uint32_t)__cvta_generic_to_shared(s);
    asm volatile("cp.async.cg.shared.global [%0], [%1], 16;" :: "r"(sa), "l"(g));
}
__device__ __forceinline__ void ldsm_x4(uint32_t& r0, uint32_t& r1, uint32_t& r2, uint32_t& r3,
                                        uint32_t a) {
    asm volatile("ldmatrix.sync.aligned.m8n8.x4.shared.b16 {%0,%1,%2,%3}, [%4];"
                 : "=r"(r0), "=r"(r1), "=r"(r2), "=r"(r3) : "r"(a));
}
__device__ __forceinline__ void ldsm_x4_t(uint32_t& r0, uint32_t& r1, uint32_t& r2, uint32_t& r3,
                                          uint32_t a) {
    asm volatile("ldmatrix.sync.aligned.m8n8.x4.trans.shared.b16 {%0,%1,%2,%3}, [%4];"
                 : "=r"(r0), "=r"(r1), "=r"(r2), "=r"(r3) : "r"(a));
}
__device__ __forceinline__ void mma16816(float* c, const uint32_t* a, const uint32_t* b) {
    asm volatile("mma.sync.aligned.m16n8k16.row.col.f32.bf16.bf16.f32 "
                 "{%0,%1,%2,%3}, {%4,%5,%6,%7}, {%8,%9}, {%0,%1,%2,%3};"
                 : "+f"(c[0]), "+f"(c[1]), "+f"(c[2]), "+f"(c[3])
                 : "r"(a[0]), "r"(a[1]), "r"(a[2]), "r"(a[3]), "r"(b[0]), "r"(b[1]));
}

// ---------------------------------------------------------------------------
// LayerNorm: one block per row (C=1024), 256 threads -> triple-bf16 A-side.
// ---------------------------------------------------------------------------
__global__ void ln_kernel(const float* __restrict__ x, const float* __restrict__ g,
                          const float* __restrict__ b, __nv_bfloat16* __restrict__ out)
{
    __shared__ float red[16];
    const int row = blockIdx.x;
    const int t   = threadIdx.x;

    float4 v = ((const float4*)(x + (size_t)row * C_))[t];

    float s = v.x + v.y + v.z + v.w;
    #pragma unroll
    for (int o = 16; o; o >>= 1) s += __shfl_xor_sync(0xffffffffu, s, o);
    if ((t & 31) == 0) red[t >> 5] = s;
    __syncthreads();
    if (t < 8) {
        float u = red[t];
        #pragma unroll
        for (int o = 4; o; o >>= 1) u += __shfl_xor_sync(0xffu, u, o);
        if (t == 0) red[8] = u;
    }
    __syncthreads();
    const float mean = red[8] * (1.0f / C_);

    float dx = v.x - mean, dy = v.y - mean, dz = v.z - mean, dw = v.w - mean;
    float sq = dx*dx + dy*dy + dz*dz + dw*dw;
    #pragma unroll
    for (int o = 16; o; o >>= 1) sq += __shfl_xor_sync(0xffffffffu, sq, o);
    __syncthreads();
    if ((t & 31) == 0) red[t >> 5] = sq;
    __syncthreads();
    if (t < 8) {
        float u = red[t];
        #pragma unroll
        for (int o = 4; o; o >>= 1) u += __shfl_xor_sync(0xffu, u, o);
        if (t == 0) red[9] = u;
    }
    __syncthreads();
    const float rstd = rsqrtf(red[9] * (1.0f / C_) + 1e-5f);

    float4 gg = ((const float4*)g)[t];
    float4 bb = ((const float4*)b)[t];
    float o0 = dx * rstd * gg.x + bb.x;
    float o1 = dy * rstd * gg.y + bb.y;
    float o2 = dz * rstd * gg.z + bb.z;
    float o3 = dw * rstd * gg.w + bb.w;

    uint32_t w[6];
    split_pair(o0, o1, w[0], w[1], w[2]);
    split_pair(o2, o3, w[3], w[4], w[5]);
    uint2* dst = (uint2*)(out + (size_t)row * K3 + 12 * t);
    dst[0] = make_uint2(w[0], w[1]);
    dst[1] = make_uint2(w[2], w[3]);
    dst[2] = make_uint2(w[4], w[5]);
}

// ---------------------------------------------------------------------------
// Repack Wq/Wk/Wv ([H,C,Dh]) into triple-row bf16 [3K, 3C] (B-side pattern)
// ---------------------------------------------------------------------------
__global__ void repack3_kernel(const float* __restrict__ Wq, const float* __restrict__ Wk,
                               const float* __restrict__ Wv, __nv_bfloat16* __restrict__ W3)
{
    int idx = blockIdx.x * 256 + threadIdx.x;          // over C_*N3
    if (idx >= C_ * N3) return;
    int k  = idx / N3;
    int n  = idx - k * N3;
    int wh = n >> 10;
    int nn = n & 1023;
    int h  = nn >> 6, d = nn & 63;
    const float* src = (wh == 0) ? Wq : (wh == 1) ? Wk : Wv;
    float w = src[(size_t)h * C_ * 64 + (size_t)k * 64 + d];
    uint32_t hb = bfbits(w);
    uint32_t lb = bfbits(w - bf2f(hb));
    W3[(size_t)(3*k+0) * N3 + n] = __ushort_as_bfloat16((unsigned short)hb);
    W3[(size_t)(3*k+1) * N3 + n] = __ushort_as_bfloat16((unsigned short)hb);
    W3[(size_t)(3*k+2) * N3 + n] = __ushort_as_bfloat16((unsigned short)lb);
}

// Convert [C,C] fp32 weight into triple-row bf16 [3C, C] (B-side pattern)
__global__ void conv3_kernel(const float* __restrict__ W, __nv_bfloat16* __restrict__ W3)
{
    int idx = blockIdx.x * 256 + threadIdx.x;          // over C_*C_
    if (idx >= C_ * C_) return;
    int k = idx >> 10, n = idx & 1023;
    float w = W[idx];
    uint32_t hb = bfbits(w);
    uint32_t lb = bfbits(w - bf2f(hb));
    W3[(size_t)(3*k+0) * C_ + n] = __ushort_as_bfloat16((unsigned short)hb);
    W3[(size_t)(3*k+1) * C_ + n] = __ushort_as_bfloat16((unsigned short)hb);
    W3[(size_t)(3*k+2) * C_ + n] = __ushort_as_bfloat16((unsigned short)lb);
}

// ---------------------------------------------------------------------------
// Tensor-core GEMM (bf16 mma.sync, fp32 accum), 3-stage cp.async pipeline.
//   EPI 0: fp32 store
//   EPI 1: fp32 store of acc + bias + res
//   EPI 2: relu(acc + bias) -> triple-bf16 (A-side), stride 3N
//   EPI 3: QKV split epilogue: Q (scaled, A-side) -> Cout, K (B-side) -> kout,
//          V (triple-rows) -> vout.
// ---------------------------------------------------------------------------
template<int EPI>
__global__ void __launch_bounds__(256, 2) mma_gemm(
    const __nv_bfloat16* __restrict__ A,   // [M_, K3]
    const __nv_bfloat16* __restrict__ Bm,  // [K3, N]
    const float* __restrict__ bias,
    const float* __restrict__ res,
    void* __restrict__ Cout, int N,
    __nv_bfloat16* __restrict__ kout,
    __nv_bfloat16* __restrict__ vout)
{
    __shared__ __nv_bfloat16 As[3][128][40];    // 80B row stride
    __shared__ __nv_bfloat16 Bs[3][32][168];    // 336B row stride (= 80 mod 128)

    const int tid  = threadIdx.x;
    const int wid  = tid >> 5, lane = tid & 31;
    const int wm   = wid & 1,  wn   = wid >> 1;    // warp grid 2x4, warp tile 64x32
    const int g    = lane >> 2, tig = lane & 3;
    const int row0 = blockIdx.y * 128, col0 = blockIdx.x * 128;

    const int ar = tid >> 2,  ac = (tid & 3) << 3;
    const int br = tid >> 4,  bc = (tid & 15) << 3;

    const int lrow = lane & 15;
    const int lcol = (lane >> 4) << 3;

    float acc[4][4][4];
    #pragma unroll
    for (int i = 0; i < 4; i++)
        #pragma unroll
        for (int j = 0; j < 4; j++)
            #pragma unroll
            for (int q = 0; q < 4; q++) acc[i][j][q] = 0.f;

    #define LOAD_CHUNK(it_, st_) do {                                          \
        const int _k0 = (it_) * 32;                                            \
        cp16(&As[st_][ar][ac],      A  + (size_t)(row0 + ar) * K3 + _k0 + ac); \
        cp16(&As[st_][ar + 64][ac], A  + (size_t)(row0 + ar + 64) * K3 + _k0 + ac); \
        cp16(&Bs[st_][br][bc],      Bm + (size_t)(_k0 + br) * N + col0 + bc); \
        cp16(&Bs[st_][br + 16][bc], Bm + (size_t)(_k0 + br + 16) * N + col0 + bc); \
        asm volatile("cp.async.commit_group;");                                \
    } while (0)

    const int nIter = K3 / 32;   // 96
    LOAD_CHUNK(0, 0);
    LOAD_CHUNK(1, 1);

    for (int it = 0; it < nIter; ++it) {
        const int buf = it % 3;
        if (it + 2 < nIter) {
            asm volatile("cp.async.wait_group 1;");
        } else {
            asm volatile("cp.async.wait_group 0;");
        }
        __syncthreads();
        if (it + 2 < nIter) LOAD_CHUNK(it + 2, (it + 2) % 3);

        #pragma unroll
        for (int ks = 0; ks < 2; ++ks) {
            uint32_t a[4][4], b[4][2];
            #pragma unroll
            for (int mt = 0; mt < 4; ++mt) {
                uint32_t addr = (uint32_t)__cvta_generic_to_shared(
                    &As[buf][wm*64 + mt*16 + lrow][ks*16 + lcol]);
                ldsm_x4(a[mt][0], a[mt][1], a[mt][2], a[mt][3], addr);
            }
            #pragma unroll
            for (int np = 0; np < 2; ++np) {
                uint32_t addr = (uint32_t)__cvta_generic_to_shared(
                    &Bs[buf][ks*16 + lrow][wn*32 + np*16 + lcol]);
                ldsm_x4_t(b[np*2][0], b[np*2][1], b[np*2+1][0], b[np*2+1][1], addr);
            }
            #pragma unroll
            for (int mt = 0; mt < 4; ++mt)
                #pragma unroll
                for (int nt = 0; nt < 4; ++nt)
                    mma16816(acc[mt][nt], a[mt], b[nt]);
        }
    }
    #undef LOAD_CHUNK

    const float QSCALE = 0.125f * 1.44269504f;   // used by EPI 3 (Q third)

    #pragma unroll
    for (int mt = 0; mt < 4; ++mt) {
        #pragma unroll
        for (int nt = 0; nt < 4; ++nt) {
            const int r = row0 + wm*64 + mt*16 + g;
            const int c = col0 + wn*32 + nt*8 + 2*tig;
            float v0 = acc[mt][nt][0], v1 = acc[mt][nt][1];
            float v2 = acc[mt][nt][2], v3 = acc[mt][nt][3];
            if (EPI == 0) {
                float* C = (float*)Cout;
                *(float2*)(C + (size_t)r * N + c)       = make_float2(v0, v1);
                *(float2*)(C + (size_t)(r + 8) * N + c) = make_float2(v2, v3);
            } else if (EPI == 1) {
                float2 bb = *(const float2*)(bias + c);
                float2 r0 = *(const float2*)(res + (size_t)r * N + c);
                float2 r1 = *(const float2*)(res + (size_t)(r + 8) * N + c);
                float* C = (float*)Cout;
                *(float2*)(C + (size_t)r * N + c)       = make_float2(v0 + bb.x + r0.x, v1 + bb.y + r0.y);
                *(float2*)(C + (size_t)(r + 8) * N + c) = make_float2(v2 + bb.x + r1.x, v3 + bb.y + r1.y);
            } else if (EPI == 2) {
                float2 bb = *(const float2*)(bias + c);
                v0 = fmaxf(v0 + bb.x, 0.f); v1 = fmaxf(v1 + bb.y, 0.f);
                v2 = fmaxf(v2 + bb.x, 0.f); v3 = fmaxf(v3 + bb.y, 0.f);
                __nv_bfloat16* O = (__nv_bfloat16*)Cout;
                uint32_t w0, w1, w2;
                split_pair(v0, v1, w0, w1, w2);
                uint32_t* q = (uint32_t*)(O + (size_t)r * (3*N) + 3*c);
                q[0] = w0; q[1] = w1; q[2] = w2;
                split_pair(v2, v3, w0, w1, w2);
                q = (uint32_t*)(O + (size_t)(r + 8) * (3*N) + 3*c);
                q[0] = w0; q[1] = w1; q[2] = w2;
            } else {
                // EPI 3: QKV split
                const int third = c >> 10;
                const int nn = c & 1023;
                const int hh = nn >> 6, d = nn & 63;
                if (third == 0) {
                    __nv_bfloat16* Q3 = (__nv_bfloat16*)Cout;
                    uint32_t w0, w1, w2;
                    split_pair(v0 * QSCALE, v1 * QSCALE, w0, w1, w2);
                    uint32_t* q = (uint32_t*)(Q3 + (size_t)r * K3 + 3*(hh*64 + d));
                    q[0] = w0; q[1] = w1; q[2] = w2;
                    split_pair(v2 * QSCALE, v3 * QSCALE, w0, w1, w2);
                    q = (uint32_t*)(Q3 + (size_t)(r + 8) * K3 + 3*(hh*64 + d));
                    q[0] = w0; q[1] = w1; q[2] = w2;
                } else if (third == 1) {
                    // B-side triple: (h0|h0),(lo0|h1),(h1|lo1)
                    #pragma unroll
                    for (int rr = 0; rr < 2; rr++) {
                        float a0 = rr ? v2 : v0, a1 = rr ? v3 : v1;
                        uint32_t h0 = bfbits(a0), lo0 = bfbits(a0 - bf2f(h0));
                        uint32_t h1 = bfbits(a1), lo1 = bfbits(a1 - bf2f(h1));
                        uint32_t* q = (uint32_t*)(kout + (size_t)(r + rr*8) * K3 + 3*(hh*64 + d));
                        q[0] = h0  | (h0 << 16);
                        q[1] = lo0 | (h1 << 16);
                        q[2] = h1  | (lo1 << 16);
                    }
                } else {
                    // V triple-rows: rows 3s,3s+1 = hi, row 3s+2 = lo
                    #pragma unroll
                    for (int rr = 0; rr < 2; rr++) {
                        float a0 = rr ? v2 : v0, a1 = rr ? v3 : v1;
                        const int row = r + rr*8;
                        const int bb = row >> 10, ss = row & 1023;
                        uint32_t h0 = bfbits(a0), lo0 = bfbits(a0 - bf2f(h0));
                        uint32_t h1 = bfbits(a1), lo1 = bfbits(a1 - bf2f(h1));
                        uint32_t hhw = h0 | (h1 << 16), llw = lo0 | (lo1 << 16);
                        size_t off = ((size_t)(bb*H_ + hh)*3*T_ + 3*ss)*64 + d;
                        *(uint32_t*)(vout + off)       = hhw;
                        *(uint32_t*)(vout + off + 64)  = hhw;
                        *(uint32_t*)(vout + off + 128) = llw;
                    }
                }
            }
        }
    }
}

// ---------------------------------------------------------------------------
// Tensor-core flash attention (bf16x3, causal), Q-tile 128 x K-tile 64.
// Q/K/V tiles are PRE-CONVERTED (by the QKV GEMM epilogue) — loads are plain
// cp.async of bf16; no conversion math in the loop.
// ---------------------------------------------------------------------------
#define QS_STRIDE 200   // bf16; 400B row stride
#define VS_STRIDE 72    // bf16; 144B row stride

__global__ void __launch_bounds__(256, 1) attn_mma_kernel(
    const __nv_bfloat16* __restrict__ q3,
    const __nv_bfloat16* __restrict__ k3,
    const __nv_bfloat16* __restrict__ v3,
    __nv_bfloat16* __restrict__ out)
{
    extern __shared__ __nv_bfloat16 sm[];
    __nv_bfloat16* Qs = sm;                        // [128][200] (192 used)
    __nv_bfloat16* Ks = Qs + 128*QS_STRIDE;        // [64][200]  (192 used)
    __nv_bfloat16* Vs = Ks + 64*QS_STRIDE;         // [192][72]  (64 used)
    __nv_bfloat16* Ps = Vs + 192*VS_STRIDE;        // [128][200] (192 used)

    const int tid  = threadIdx.x;
    const int wid  = tid >> 5, lane = tid & 31;
    const int g    = lane >> 2, tig = lane & 3;
    const int qt   = (int)(gridDim.x - 1 - blockIdx.x);
    const int h    = blockIdx.y, b = blockIdx.z;
    const int q0   = qt * 128;
    const int mrow0 = wid * 16;

    // ---- Q tile: 128 rows x 384B, cp.async (2 threads/row, 12 chunks each) ----
    {
        const int row  = tid >> 1;
        const int half = tid & 1;
        const __nv_bfloat16* src = q3 + (size_t)(b*T_ + q0 + row) * K3 + h*192 + half*96;
        __nv_bfloat16* dst = Qs + row * QS_STRIDE + half*96;
        #pragma unroll
        for (int j = 0; j < 12; j++) cp16(dst + j*8, src + j*8);
        asm volatile("cp.async.commit_group;");
    }

    float o[8][4];
    #pragma unroll
    for (int nb = 0; nb < 8; nb++)
        #pragma unroll
        for (int j = 0; j < 4; j++) o[nb][j] = 0.f;
    float m0 = -1e30f, m1 = -1e30f, l0 = 0.f, l1 = 0.f;

    const int r0g = q0 + mrow0 + g;
    const int r1g = r0g + 8;
    const int ktMax = 2*qt + 1;
    const __nv_bfloat16* vbase = v3 + (size_t)(b*H_ + h)*3*T_*64;

    for (int kt = 0; kt <= ktMax; kt++) {
        const int k0 = kt * 64;
        const bool need_mask = (kt >= 2*qt);
        __syncthreads();   // prior iter's smem reads done

        // ---- K tile: 64 rows x 384B (4 threads/row, 6 chunks) ----
        {
            const int row = tid >> 2;
            const int qr  = tid & 3;
            const __nv_bfloat16* src = k3 + (size_t)(b*T_ + k0 + row) * K3 + h*192 + qr*48;
            __nv_bfloat16* dst = Ks + row * QS_STRIDE + qr*48;
            #pragma unroll
            for (int j = 0; j < 6; j++) cp16(dst + j*8, src + j*8);
        }
        // ---- V tile: 192 rows x 128B (1536 chunks, 6/thread) ----
        {
            #pragma unroll
            for (int i = 0; i < 6; i++) {
                int id = tid + i*256;
                int rr = id >> 3, cc = id & 7;
                cp16(Vs + rr*VS_STRIDE + cc*8, vbase + (size_t)(3*k0 + rr)*64 + cc*8);
            }
        }
        asm volatile("cp.async.commit_group;");
        asm volatile("cp.async.wait_group 0;");
        __syncthreads();

        // ---- S = Q K^T ----
        float sacc[8][4];
        #pragma unroll
        for (int nb = 0; nb < 8; nb++)
            #pragma unroll
            for (int j = 0; j < 4; j++) sacc[nb][j] = 0.f;

        const int part = lane >> 3, lr = lane & 7;
        #pragma unroll
        for (int ks = 0; ks < 12; ks++) {
            uint32_t a[4];
            uint32_t aa = (uint32_t)__cvta_generic_to_shared(
                &Qs[(mrow0 + (lane & 15)) * QS_STRIDE + ks*16 + ((lane >> 4) << 3)]);
            ldsm_x4(a[0], a[1], a[2], a[3], aa);
            uint32_t bb[8][2];
            #pragma unroll
            for (int q = 0; q < 4; q++) {
                const int nrow = q*16 + ((part & 2) ? 8 : 0) + lr;
                const int kofs = ks*16 + ((part & 1) ? 8 : 0);
                uint32_t ba = (uint32_t)__cvta_generic_to_shared(&Ks[nrow * QS_STRIDE + kofs]);
                ldsm_x4(bb[q*2][0], bb[q*2][1], bb[q*2+1][0], bb[q*2+1][1], ba);
            }
            #pragma unroll
            for (int nb = 0; nb < 8; nb++) mma16816(sacc[nb], a, bb[nb]);
        }

        if (need_mask) {
            #pragma unroll
            for (int nb = 0; nb < 8; nb++) {
                const int c0 = k0 + nb*8 + 2*tig;
                if (c0     > r0g) sacc[nb][0] = -1e30f;
                if (c0 + 1 > r0g) sacc[nb][1] = -1e30f;
                if (c0     > r1g) sacc[nb][2] = -1e30f;
                if (c0 + 1 > r1g) sacc[nb][3] = -1e30f;
            }
        }

        // ---- online softmax (base 2; scale folded into Q) ----
        float rm0 = -1e30f, rm1 = -1e30f;
        #pragma unroll
        for (int nb = 0; nb < 8; nb++) {
            rm0 = fmaxf(rm0, fmaxf(sacc[nb][0], sacc[nb][1]));
            rm1 = fmaxf(rm1, fmaxf(sacc[nb][2], sacc[nb][3]));
        }
        rm0 = fmaxf(rm0, __shfl_xor_sync(0xffffffffu, rm0, 1));
        rm0 = fmaxf(rm0, __shfl_xor_sync(0xffffffffu, rm0, 2));
        rm1 = fmaxf(rm1, __shfl_xor_sync(0xffffffffu, rm1, 1));
        rm1 = fmaxf(rm1, __shfl_xor_sync(0xffffffffu, rm1, 2));

        const float mn0 = fmaxf(m0, rm0), mn1 = fmaxf(m1, rm1);
        const float al0 = exp2f(m0 - mn0), al1 = exp2f(m1 - mn1);
        m0 = mn0; m1 = mn1;

        float rs0 = 0.f, rs1 = 0.f;
        #pragma unroll
        for (int nb = 0; nb < 8; nb++) {
            const float p0 = exp2f(sacc[nb][0] - mn0);
            const float p1 = exp2f(sacc[nb][1] - mn0);
            const float p2 = exp2f(sacc[nb][2] - mn1);
            const float p3 = exp2f(sacc[nb][3] - mn1);
            rs0 += p0 + p1;  rs1 += p2 + p3;
            uint32_t w0, w1, w2;
            split_pair(p0, p1, w0, w1, w2);
            uint32_t* d0 = (uint32_t*)(Ps + (mrow0 + g) * QS_STRIDE + 3*(nb*8 + 2*tig));
            d0[0] = w0; d0[1] = w1; d0[2] = w2;
            split_pair(p2, p3, w0, w1, w2);
            uint32_t* d1 = (uint32_t*)(Ps + (mrow0 + g + 8) * QS_STRIDE + 3*(nb*8 + 2*tig));
            d1[0] = w0; d1[1] = w1; d1[2] = w2;
        }
        rs0 += __shfl_xor_sync(0xffffffffu, rs0, 1);
        rs0 += __shfl_xor_sync(0xffffffffu, rs0, 2);
        rs1 += __shfl_xor_sync(0xffffffffu, rs1, 1);
        rs1 += __shfl_xor_sync(0xffffffffu, rs1, 2);
        l0 = l0 * al0 + rs0;
        l1 = l1 * al1 + rs1;
        #pragma unroll
        for (int nb = 0; nb < 8; nb++) {
            o[nb][0] *= al0; o[nb][1] *= al0;
            o[nb][2] *= al1; o[nb][3] *= al1;
        }
        __syncthreads();

        // ---- O += P V ----
        #pragma unroll
        for (int ks = 0; ks < 12; ks++) {
            uint32_t a[4];
            uint32_t aa = (uint32_t)__cvta_generic_to_shared(
                &Ps[(mrow0 + (lane & 15)) * QS_STRIDE + ks*16 + ((lane >> 4) << 3)]);
            ldsm_x4(a[0], a[1], a[2], a[3], aa);
            uint32_t bv[8][2];
            #pragma unroll
            for (int dq = 0; dq < 4; dq++) {
                uint32_t ba = (uint32_t)__cvta_generic_to_shared(
                    &Vs[(ks*16 + (lane & 15)) * VS_STRIDE + dq*16 + ((lane >> 4) << 3)]);
                ldsm_x4_t(bv[dq*2][0], bv[dq*2][1], bv[dq*2+1][0], bv[dq*2+1][1], ba);
            }
            #pragma unroll
            for (int nb = 0; nb < 8; nb++) mma16816(o[nb], a, bv[nb]);
        }
    }

    const float inv0 = 1.0f / l0, inv1 = 1.0f / l1;
    #pragma unroll
    for (int nb = 0; nb < 8; nb++) {
        const int col = h*64 + nb*8 + 2*tig;
        uint32_t w0, w1, w2;
        split_pair(o[nb][0]*inv0, o[nb][1]*inv0, w0, w1, w2);
        uint32_t* d0 = (uint32_t*)(out + (size_t)(b*T_ + r0g) * (size_t)K3 + 3*col);
        d0[0] = w0; d0[1] = w1; d0[2] = w2;
        split_pair(o[nb][2]*inv1, o[nb][3]*inv1, w0, w1, w2);
        uint32_t* d1 = (uint32_t*)(out + (size_t)(b*T_ + r1g) * (size_t)K3 + 3*col);
        d1[0] = w0; d1[1] = w1; d1[2] = w2;
    }
}

// ---------------------------------------------------------------------------
// Launch
// ---------------------------------------------------------------------------
static const int ATTN_SMEM = (128*QS_STRIDE + 64*QS_STRIDE + 192*VS_STRIDE + 128*QS_STRIDE)
                             * (int)sizeof(__nv_bfloat16);   // 155,648 B

extern "C" void kernel_launch(void* const* d_in, const int* in_sizes, int n_in,
                              void* d_out, int out_size)
{
    const float* x     = (const float*)d_in[0];
    const float* Wq    = (const float*)d_in[1];
    const float* Wk    = (const float*)d_in[2];
    const float* Wv    = (const float*)d_in[3];
    const float* Wproj = (const float*)d_in[4];
    const float* bproj = (const float*)d_in[5];
    const float* W1    = (const float*)d_in[6];
    const float* b1    = (const float*)d_in[7];
    const float* W2    = (const float*)d_in[8];
    const float* b2    = (const float*)d_in[9];
    const float* g1    = (const float*)d_in[10];
    const float* be1   = (const float*)d_in[11];
    const float* g2    = (const float*)d_in[12];
    const float* be2   = (const float*)d_in[13];
    float* out = (float*)d_out;

    __nv_bfloat16 *xn3, *wqkv3, *q3, *k3, *v3, *attn3, *h3, *wp3, *w13, *w23;
    float *x1;
    cudaGetSymbolAddress((void**)&xn3,   g_xn3);
    cudaGetSymbolAddress((void**)&wqkv3, g_wqkv3);
    cudaGetSymbolAddress((void**)&q3,    g_q3);
    cudaGetSymbolAddress((void**)&k3,    g_k3);
    cudaGetSymbolAddress((void**)&v3,    g_v3);
    cudaGetSymbolAddress((void**)&attn3, g_attn3);
    cudaGetSymbolAddress((void**)&x1,    g_x1);
    cudaGetSymbolAddress((void**)&h3,    g_h3);
    cudaGetSymbolAddress((void**)&wp3,   g_wp3);
    cudaGetSymbolAddress((void**)&w13,   g_w13);
    cudaGetSymbolAddress((void**)&w23,   g_w23);

    cudaFuncSetAttribute(attn_mma_kernel, cudaFuncAttributeMaxDynamicSharedMemorySize, ATTN_SMEM);

    // weight conversions (triple-bf16)
    repack3_kernel<<<(C_*N3 + 255)/256, 256>>>(Wq, Wk, Wv, wqkv3);
    conv3_kernel  <<<(C_*C_ + 255)/256, 256>>>(Wproj, wp3);
    conv3_kernel  <<<(C_*C_ + 255)/256, 256>>>(W1, w13);
    conv3_kernel  <<<(C_*C_ + 255)/256, 256>>>(W2, w23);

    // 1. LN1 -> triple bf16
    ln_kernel<<<M_, 256>>>(x, g1, be1, xn3);
    // 2. fused QKV GEMM -> Q3/K3/V3 in attention-ready layouts (EPI 3)
    mma_gemm<3><<<dim3(N3/128, M_/128), 256>>>(xn3, wqkv3, nullptr, nullptr, q3, N3, k3, v3);
    // 3. causal flash attention -> triple bf16
    attn_mma_kernel<<<dim3(T_/128, H_, B_), 256, ATTN_SMEM>>>(q3, k3, v3, attn3);
    // 4. proj + bias + residual -> fp32 x1
    mma_gemm<1><<<dim3(C_/128, M_/128), 256>>>(attn3, wp3, bproj, x, x1, C_, nullptr, nullptr);
    // 5. LN2 -> triple bf16
    ln_kernel<<<M_, 256>>>(x1, g2, be2, xn3);
    // 6. fc1 + ReLU -> triple bf16
    mma_gemm<2><<<dim3(C_/128, M_/128), 256>>>(xn3, w13, b1, nullptr, h3, C_, nullptr, nullptr);
    // 7. fc2 + bias + residual -> out (fp32)
    mma_gemm<1><<<dim3(C_/128, M_/128), 256>>>(h3, w23, b2, x1, out, C_, nullptr, nullptr);
}